// round 5
// baseline (speedup 1.0000x reference)
#include <cuda_runtime.h>

#define BB 128
#define TT 2048
#define DD 64
#define HH 128
#define OO 32

typedef unsigned long long ull;

// Scratch (allocation-free rule: __device__ globals)
__device__ float g_xp0[(size_t)BB * TT * HH];  // layer0 input projection
__device__ float g_h1[(size_t)BB * TT * HH];   // layer1 hidden states

// ---------------------------------------------------------------------------
// fast tanh, short serial chain (~52 cyc): no clamp needed --
// ex2(+inf)=inf -> rcp=0 -> t=1 saturates correctly. ~1e-6 rel err.
__device__ __forceinline__ float fast_tanh(float x) {
    float ax = fabsf(x);
    float y  = ax * 2.8853900817779268f;   // 2*log2(e)
    float e;  asm("ex2.approx.f32 %0, %1;" : "=f"(e) : "f"(y));
    float d  = e + 1.0f;
    float r;  asm("rcp.approx.f32 %0, %1;" : "=f"(r) : "f"(d));
    float t  = fmaf(-2.0f, r, 1.0f);
    return copysignf(t, x);
}

// 128-long dot product with c0 folded into the accumulator init.
// Weights in registers as 64 packed f32x2, vector from smem via LDS.128
// (broadcast). 2 accumulator chains.
__device__ __forceinline__ float dot128_c0(const ull* w, const float* v, float c0) {
    ull a0, a1 = 0ull;
    asm("mov.b64 %0, {%1, %2};" : "=l"(a0) : "f"(c0), "f"(0.0f));
    const ulonglong2* v2 = (const ulonglong2*)v;
#pragma unroll
    for (int j = 0; j < 32; j++) {
        ulonglong2 p = v2[j];
        asm("fma.rn.f32x2 %0, %1, %2, %0;" : "+l"(a0) : "l"(w[2 * j]),     "l"(p.x));
        asm("fma.rn.f32x2 %0, %1, %2, %0;" : "+l"(a1) : "l"(w[2 * j + 1]), "l"(p.y));
    }
    asm("add.rn.f32x2 %0, %0, %1;" : "+l"(a0) : "l"(a1));
    float lo = __uint_as_float((unsigned)(a0 & 0xffffffffu));
    float hi = __uint_as_float((unsigned)(a0 >> 32));
    return lo + hi;
}

// ---------------------------------------------------------------------------
// Kernel 1: xp0[b,t,h] = sum_d x[b,t,d]*W_ih0[h,d] + b_ih0[h] + b_hh0[h]
// smem-tiled GEMM, 128x128 block tile, K=64, 8x8 register tile per thread.
// At scalar-FFMA roofline (125us ~= 119us model) — do not touch.
#define XPAD 132
__global__ void __launch_bounds__(256)
xproj_kernel(const float* __restrict__ x, const float* __restrict__ Wih0,
             const float* __restrict__ bih0, const float* __restrict__ bhh0) {
    extern __shared__ float sm[];
    float* xsT = sm;                 // [64][XPAD] : xsT[d][r]
    float* wsT = sm + 64 * XPAD;     // [64][XPAD] : wsT[d][h]
    int tid  = threadIdx.x;
    int row0 = blockIdx.x * 128;

    const float4* xg = (const float4*)(x + (size_t)row0 * DD);
#pragma unroll
    for (int j = 0; j < 8; j++) {
        int idx = tid + 256 * j;
        float4 v = xg[idx];
        int r = idx >> 4, d4 = (idx & 15) << 2;
        xsT[(d4 + 0) * XPAD + r] = v.x;
        xsT[(d4 + 1) * XPAD + r] = v.y;
        xsT[(d4 + 2) * XPAD + r] = v.z;
        xsT[(d4 + 3) * XPAD + r] = v.w;
    }
    const float4* wg = (const float4*)Wih0;
#pragma unroll
    for (int j = 0; j < 8; j++) {
        int idx = tid + 256 * j;
        float4 v = wg[idx];
        int h = idx >> 4, d4 = (idx & 15) << 2;
        wsT[(d4 + 0) * XPAD + h] = v.x;
        wsT[(d4 + 1) * XPAD + h] = v.y;
        wsT[(d4 + 2) * XPAD + h] = v.z;
        wsT[(d4 + 3) * XPAD + h] = v.w;
    }

    int tx = tid & 15, ty = tid >> 4;
    int c0 = tx * 8, r0 = ty * 8;
    float acc[8][8];
#pragma unroll
    for (int j = 0; j < 8; j++) {
        float bb = bih0[c0 + j] + bhh0[c0 + j];
#pragma unroll
        for (int i = 0; i < 8; i++) acc[i][j] = bb;
    }
    __syncthreads();

#pragma unroll 8
    for (int k = 0; k < 64; k++) {
        float4 a0 = *(const float4*)&xsT[k * XPAD + r0];
        float4 a1 = *(const float4*)&xsT[k * XPAD + r0 + 4];
        float4 b0 = *(const float4*)&wsT[k * XPAD + c0];
        float4 b1 = *(const float4*)&wsT[k * XPAD + c0 + 4];
        float av[8] = {a0.x, a0.y, a0.z, a0.w, a1.x, a1.y, a1.z, a1.w};
        float bv[8] = {b0.x, b0.y, b0.z, b0.w, b1.x, b1.y, b1.z, b1.w};
#pragma unroll
        for (int i = 0; i < 8; i++)
#pragma unroll
            for (int j = 0; j < 8; j++)
                acc[i][j] = fmaf(av[i], bv[j], acc[i][j]);
    }

    float* og = g_xp0 + (size_t)row0 * HH;
#pragma unroll
    for (int i = 0; i < 8; i++) {
        *(float4*)&og[(size_t)(r0 + i) * HH + c0] =
            make_float4(acc[i][0], acc[i][1], acc[i][2], acc[i][3]);
        *(float4*)&og[(size_t)(r0 + i) * HH + c0 + 4] =
            make_float4(acc[i][4], acc[i][5], acc[i][6], acc[i][7]);
    }
}

// ---------------------------------------------------------------------------
// Kernel 2: sequential scan, branch-free body, single __syncthreads per step
// (R4 showed named barriers regress). Tail trimmed: p1 folded into dot init,
// short tanh, prefetch LDG issued at top of step.
__global__ void __launch_bounds__(384, 1)
scan_kernel(const float* __restrict__ Whh0, const float* __restrict__ Wih1,
            const float* __restrict__ Whh1, const float* __restrict__ bih1,
            const float* __restrict__ bhh1, const int* __restrict__ lengths) {
    __shared__ __align__(16) float h0buf[2][HH];
    __shared__ __align__(16) float h1buf[2][HH];
    __shared__ __align__(16) float p1buf[2][HH];

    int b   = blockIdx.x;
    int L   = lengths[b];
    int tid = threadIdx.x;
    int grp = tid >> 7;
    int row = tid & 127;
    bool isg0 = (grp == 0), isg1 = (grp == 1), isg2 = (grp == 2);

    const float* Wrow = (isg0 ? Whh0 : (isg1 ? Wih1 : Whh1)) + (size_t)row * HH;
    ull w[64];
#pragma unroll
    for (int j = 0; j < 64; j++) w[j] = ((const ull*)Wrow)[j];

    // c0 sources: g0 = streamed xp ring; g1 = bias (constant in ring);
    // g2 = p1buf value loaded per step (folded into dot init).
    const float* xp_base = g_xp0 + (size_t)b * TT * HH + row;
    float cinit = isg1 ? (bih1[row] + bhh1[row]) : 0.f;
    float xp[4];
#pragma unroll
    for (int i = 0; i < 4; i++) xp[i] = isg0 ? xp_base[(size_t)i * HH] : cinit;

    if (isg0) h0buf[1][row] = 0.f;   // value index -1 lives in buffer 1
    if (isg2) h1buf[1][row] = 0.f;

    // parity-indexed pointers (pa = s&1):
    //   g0: read h0buf[pb], write h0buf[pa]
    //   g1: read h0buf[pb], write p1buf[pb]
    //   g2: read h1buf[pb], write h1buf[pa], c0 from p1buf[pa]
    const float* vrd[2];
    float*       st[2];
    const float* prd[2];
#pragma unroll
    for (int pa = 0; pa < 2; pa++) {
        int pb = pa ^ 1;
        vrd[pa] = isg2 ? h1buf[pb] : h0buf[pb];
        st[pa]  = isg0 ? &h0buf[pa][row] : (isg1 ? &p1buf[pb][row] : &h1buf[pa][row]);
        prd[pa] = &p1buf[pa][row];
    }
    float* h1out = g_h1 + (size_t)b * TT * HH + row;

    __syncthreads();   // initial state visible to everyone

    int spad = ((L + 2) + 3) & ~3;
    for (int s0 = 0; s0 < spad; s0 += 4) {
#pragma unroll
        for (int u = 0; u < 4; u++) {
            int s  = s0 + u;
            int pa = u & 1;                       // s0 multiple of 4 -> static
            // early prefetch (g0 only), issued before the dot
            float t_pf = xp[u];
            if (isg0) {
                int nidx = s + 4; if (nidx > TT - 1) nidx = TT - 1;
                t_pf = __ldg(&xp_base[(size_t)nidx * HH]);
            }
            float c0 = xp[u];
            if (isg2) c0 = *prd[pa];              // p1 value s-2 (predicated LDS)
            float d  = dot128_c0(w, vrd[pa], c0);
            float th = fast_tanh(d);
            float y  = isg1 ? d : th;
            if (!isg2 || s >= 2) *st[pa] = y;     // predicated STS
            if (isg2 && (unsigned)(s - 2) < (unsigned)TT)  // predicated STG
                h1out[(size_t)(s - 2) * HH] = y;
            xp[u] = t_pf;
            __syncthreads();
        }
    }
}

// ---------------------------------------------------------------------------
// Kernel 3: out[b,t,:] = (t < L) ? h1[b,t,:] @ W_fc^T + b_fc : b_fc
__global__ void __launch_bounds__(256)
fc_kernel(const float* __restrict__ Wfc, const float* __restrict__ bfc,
          const int* __restrict__ lengths, float* __restrict__ out) {
    __shared__ __align__(16) float wfcT[HH * 33];
    __shared__ __align__(16) float h1s[32 * HH];
    __shared__ float bfcs[OO];

    int tid  = threadIdx.x;
    int row0 = blockIdx.x * 32;      // 32 | TT -> whole block is one batch b
    int b = row0 / TT;
    int L = lengths[b];

    for (int idx = tid; idx < OO * HH; idx += 256) {
        int o = idx >> 7, k = idx & 127;
        wfcT[k * 33 + o] = Wfc[idx];
    }
    if (tid < OO) bfcs[tid] = bfc[tid];
    const float4* hg = (const float4*)(g_h1 + (size_t)row0 * HH);
#pragma unroll
    for (int j = 0; j < 4; j++)
        ((float4*)h1s)[tid + 256 * j] = hg[tid + 256 * j];
    __syncthreads();

    int o  = tid & 31;
    int rg = tid >> 5;               // 8 groups x 4 rows
    int tb = row0 % TT;
#pragma unroll
    for (int i = 0; i < 4; i++) {
        int r = rg * 4 + i;
        int t = tb + r;
        float res;
        if (t < L) {
            float acc = 0.f;
#pragma unroll
            for (int k = 0; k < HH; k++)
                acc = fmaf(wfcT[k * 33 + o], h1s[r * HH + k], acc);
            res = acc + bfcs[o];
        } else {
            res = bfcs[o];
        }
        out[(size_t)(row0 + r) * OO + o] = res;
    }
}

// ---------------------------------------------------------------------------
extern "C" void kernel_launch(void* const* d_in, const int* in_sizes, int n_in,
                              void* d_out, int out_size) {
    const float* x     = (const float*)d_in[0];
    const int*   len   = (const int*)  d_in[1];
    const float* Wih0  = (const float*)d_in[2];
    const float* Whh0  = (const float*)d_in[3];
    const float* bih0  = (const float*)d_in[4];
    const float* bhh0  = (const float*)d_in[5];
    const float* Wih1  = (const float*)d_in[6];
    const float* Whh1  = (const float*)d_in[7];
    const float* bih1  = (const float*)d_in[8];
    const float* bhh1  = (const float*)d_in[9];
    const float* Wfc   = (const float*)d_in[10];
    const float* bfc   = (const float*)d_in[11];
    float* out = (float*)d_out;

    static_assert(2 * 64 * XPAD * 4 == 67584, "smem size");
    cudaFuncSetAttribute(xproj_kernel, cudaFuncAttributeMaxDynamicSharedMemorySize, 67584);
    xproj_kernel<<<(BB * TT) / 128, 256, 67584>>>(x, Wih0, bih0, bhh0);
    scan_kernel<<<BB, 384>>>(Whh0, Wih1, Whh1, bih1, bhh1, len);
    fc_kernel<<<(BB * TT) / 32, 256>>>(Wfc, bfc, len, out);
}

// round 6
// speedup vs baseline: 1.0679x; 1.0679x over previous
#include <cuda_runtime.h>

#define BB 128
#define TT 2048
#define DD 64
#define HH 128
#define OO 32

typedef unsigned long long ull;

// Scratch (allocation-free rule: __device__ globals)
__device__ float g_xp0[(size_t)BB * TT * HH];  // layer0 input projection
__device__ float g_h1[(size_t)BB * TT * HH];   // layer1 hidden states

// ---------------------------------------------------------------------------
// short tanh: no clamp needed (ex2(+inf)=inf -> rcp=0 -> t=1). ~1e-6 rel err.
__device__ __forceinline__ float fast_tanh(float x) {
    float ax = fabsf(x);
    float y  = ax * 2.8853900817779268f;   // 2*log2(e)
    float e;  asm("ex2.approx.f32 %0, %1;" : "=f"(e) : "f"(y));
    float d  = e + 1.0f;
    float r;  asm("rcp.approx.f32 %0, %1;" : "=f"(r) : "f"(d));
    float t  = fmaf(-2.0f, r, 1.0f);
    return copysignf(t, x);
}

// 128-long dot, c0 folded into accumulator init. Weights in registers as 64
// packed f32x2; vector from smem via LDS.128 (broadcast), MANUALLY
// SOFTWARE-PIPELINED one pair-group (32B) ahead so LDS latency is off the
// FMA critical path. NOTE: reads 32B past v[127] -- caller guarantees the
// buffer has in-bounds tail space.
__device__ __forceinline__ float dot128_c0(const ull* w, const float* v, float c0) {
    ull a0, a1 = 0ull;
    asm("mov.b64 %0, {%1, %2};" : "=l"(a0) : "f"(c0), "f"(0.0f));
    const ulonglong2* v2 = (const ulonglong2*)v;
    ulonglong2 q0 = v2[0];
    ulonglong2 q1 = v2[1];
#pragma unroll
    for (int j = 0; j < 30; j += 2) {
        ulonglong2 n0 = v2[j + 2];
        ulonglong2 n1 = v2[j + 3];
        asm("fma.rn.f32x2 %0, %1, %2, %0;" : "+l"(a0) : "l"(w[2 * j]),     "l"(q0.x));
        asm("fma.rn.f32x2 %0, %1, %2, %0;" : "+l"(a1) : "l"(w[2 * j + 1]), "l"(q0.y));
        asm("fma.rn.f32x2 %0, %1, %2, %0;" : "+l"(a0) : "l"(w[2 * j + 2]), "l"(q1.x));
        asm("fma.rn.f32x2 %0, %1, %2, %0;" : "+l"(a1) : "l"(w[2 * j + 3]), "l"(q1.y));
        q0 = n0; q1 = n1;
    }
    asm("fma.rn.f32x2 %0, %1, %2, %0;" : "+l"(a0) : "l"(w[60]), "l"(q0.x));
    asm("fma.rn.f32x2 %0, %1, %2, %0;" : "+l"(a1) : "l"(w[61]), "l"(q0.y));
    asm("fma.rn.f32x2 %0, %1, %2, %0;" : "+l"(a0) : "l"(w[62]), "l"(q1.x));
    asm("fma.rn.f32x2 %0, %1, %2, %0;" : "+l"(a1) : "l"(w[63]), "l"(q1.y));
    asm("add.rn.f32x2 %0, %0, %1;" : "+l"(a0) : "l"(a1));
    float lo = __uint_as_float((unsigned)(a0 & 0xffffffffu));
    float hi = __uint_as_float((unsigned)(a0 >> 32));
    return lo + hi;
}

// ---------------------------------------------------------------------------
// Kernel 1: xp0[b,t,h] = sum_d x[b,t,d]*W_ih0[h,d] + b_ih0[h] + b_hh0[h]
// At scalar-FFMA roofline (125us ~= 119us model) — do not touch.
#define XPAD 132
__global__ void __launch_bounds__(256)
xproj_kernel(const float* __restrict__ x, const float* __restrict__ Wih0,
             const float* __restrict__ bih0, const float* __restrict__ bhh0) {
    extern __shared__ float sm[];
    float* xsT = sm;                 // [64][XPAD] : xsT[d][r]
    float* wsT = sm + 64 * XPAD;     // [64][XPAD] : wsT[d][h]
    int tid  = threadIdx.x;
    int row0 = blockIdx.x * 128;

    const float4* xg = (const float4*)(x + (size_t)row0 * DD);
#pragma unroll
    for (int j = 0; j < 8; j++) {
        int idx = tid + 256 * j;
        float4 v = xg[idx];
        int r = idx >> 4, d4 = (idx & 15) << 2;
        xsT[(d4 + 0) * XPAD + r] = v.x;
        xsT[(d4 + 1) * XPAD + r] = v.y;
        xsT[(d4 + 2) * XPAD + r] = v.z;
        xsT[(d4 + 3) * XPAD + r] = v.w;
    }
    const float4* wg = (const float4*)Wih0;
#pragma unroll
    for (int j = 0; j < 8; j++) {
        int idx = tid + 256 * j;
        float4 v = wg[idx];
        int h = idx >> 4, d4 = (idx & 15) << 2;
        wsT[(d4 + 0) * XPAD + h] = v.x;
        wsT[(d4 + 1) * XPAD + h] = v.y;
        wsT[(d4 + 2) * XPAD + h] = v.z;
        wsT[(d4 + 3) * XPAD + h] = v.w;
    }

    int tx = tid & 15, ty = tid >> 4;
    int c0 = tx * 8, r0 = ty * 8;
    float acc[8][8];
#pragma unroll
    for (int j = 0; j < 8; j++) {
        float bb = bih0[c0 + j] + bhh0[c0 + j];
#pragma unroll
        for (int i = 0; i < 8; i++) acc[i][j] = bb;
    }
    __syncthreads();

#pragma unroll 8
    for (int k = 0; k < 64; k++) {
        float4 a0 = *(const float4*)&xsT[k * XPAD + r0];
        float4 a1 = *(const float4*)&xsT[k * XPAD + r0 + 4];
        float4 b0 = *(const float4*)&wsT[k * XPAD + c0];
        float4 b1 = *(const float4*)&wsT[k * XPAD + c0 + 4];
        float av[8] = {a0.x, a0.y, a0.z, a0.w, a1.x, a1.y, a1.z, a1.w};
        float bv[8] = {b0.x, b0.y, b0.z, b0.w, b1.x, b1.y, b1.z, b1.w};
#pragma unroll
        for (int i = 0; i < 8; i++)
#pragma unroll
            for (int j = 0; j < 8; j++)
                acc[i][j] = fmaf(av[i], bv[j], acc[i][j]);
    }

    float* og = g_xp0 + (size_t)row0 * HH;
#pragma unroll
    for (int i = 0; i < 8; i++) {
        *(float4*)&og[(size_t)(r0 + i) * HH + c0] =
            make_float4(acc[i][0], acc[i][1], acc[i][2], acc[i][3]);
        *(float4*)&og[(size_t)(r0 + i) * HH + c0 + 4] =
            make_float4(acc[i][4], acc[i][5], acc[i][6], acc[i][7]);
    }
}

// ---------------------------------------------------------------------------
// Kernel 2: sequential scan, R3 structure (best known): branch-free body,
// single __syncthreads per step, extra (p1) loaded at top + added after dot.
// New: pipelined dot + short tanh. Buffers in one contiguous smem array so
// the dot's 32B prefetch overrun stays in-bounds.
__global__ void __launch_bounds__(384, 1)
scan_kernel(const float* __restrict__ Whh0, const float* __restrict__ Wih1,
            const float* __restrict__ Whh1, const float* __restrict__ bih1,
            const float* __restrict__ bhh1, const int* __restrict__ lengths) {
    __shared__ __align__(16) float sbuf[6 * HH + 8];  // +8 tail pad
    float (*h0buf)[HH] = (float(*)[HH])(sbuf);            // [2][HH]
    float (*h1buf)[HH] = (float(*)[HH])(sbuf + 2 * HH);   // [2][HH]
    float (*p1buf)[HH] = (float(*)[HH])(sbuf + 4 * HH);   // [2][HH]

    int b   = blockIdx.x;
    int L   = lengths[b];
    int tid = threadIdx.x;
    int grp = tid >> 7;
    int row = tid & 127;
    bool isg0 = (grp == 0), isg1 = (grp == 1), isg2 = (grp == 2);

    const float* Wrow = (isg0 ? Whh0 : (isg1 ? Wih1 : Whh1)) + (size_t)row * HH;
    ull w[64];
#pragma unroll
    for (int j = 0; j < 64; j++) w[j] = ((const ull*)Wrow)[j];

    // c0 ring: g0 = streamed xp values; g1 = bias (constant); g2 = 0
    const float* xp_base = g_xp0 + (size_t)b * TT * HH + row;
    float cinit = isg1 ? (bih1[row] + bhh1[row]) : 0.f;
    float xp[4];
#pragma unroll
    for (int i = 0; i < 4; i++) xp[i] = isg0 ? xp_base[(size_t)i * HH] : cinit;

    if (isg0) h0buf[1][row] = 0.f;   // value index -1 lives in buffer 1
    if (isg2) h1buf[1][row] = 0.f;

    // parity-indexed pointers (pa = s&1):
    //   g0: read h0buf[pb], write h0buf[pa]
    //   g1: read h0buf[pb], write p1buf[pb]
    //   g2: read h1buf[pb], write h1buf[pa], extra-read p1buf[pa]
    const float* vrd[2];
    float*       st[2];
    const float* prd[2];
#pragma unroll
    for (int pa = 0; pa < 2; pa++) {
        int pb = pa ^ 1;
        vrd[pa] = isg2 ? h1buf[pb] : h0buf[pb];
        st[pa]  = isg0 ? &h0buf[pa][row] : (isg1 ? &p1buf[pb][row] : &h1buf[pa][row]);
        prd[pa] = &p1buf[pa][row];
    }
    float* h1out = g_h1 + (size_t)b * TT * HH + row;

    __syncthreads();   // initial state visible to everyone

    int spad = ((L + 2) + 3) & ~3;
    for (int s0 = 0; s0 < spad; s0 += 4) {
#pragma unroll
        for (int u = 0; u < 4; u++) {
            int s  = s0 + u;
            int pa = u & 1;                       // s0 multiple of 4 -> static
            float extra = *prd[pa];               // p1 value s-2 (g2 only)
            float d   = dot128_c0(w, vrd[pa], xp[u]);
            float pre = d + (isg2 ? extra : 0.f);
            float th  = fast_tanh(pre);
            float y   = isg1 ? pre : th;
            if (!isg2 || s >= 2) *st[pa] = y;     // predicated STS
            if (isg2 && (unsigned)(s - 2) < (unsigned)TT)  // predicated STG
                h1out[(size_t)(s - 2) * HH] = y;
            if (isg0) {                           // predicated prefetch LDG
                int nidx = s + 4; if (nidx > TT - 1) nidx = TT - 1;
                xp[u] = __ldg(&xp_base[(size_t)nidx * HH]);
            }
            __syncthreads();
        }
    }
}

// ---------------------------------------------------------------------------
// Kernel 3: out[b,t,:] = (t < L) ? h1[b,t,:] @ W_fc^T + b_fc : b_fc
__global__ void __launch_bounds__(256)
fc_kernel(const float* __restrict__ Wfc, const float* __restrict__ bfc,
          const int* __restrict__ lengths, float* __restrict__ out) {
    __shared__ __align__(16) float wfcT[HH * 33];
    __shared__ __align__(16) float h1s[32 * HH];
    __shared__ float bfcs[OO];

    int tid  = threadIdx.x;
    int row0 = blockIdx.x * 32;      // 32 | TT -> whole block is one batch b
    int b = row0 / TT;
    int L = lengths[b];

    for (int idx = tid; idx < OO * HH; idx += 256) {
        int o = idx >> 7, k = idx & 127;
        wfcT[k * 33 + o] = Wfc[idx];
    }
    if (tid < OO) bfcs[tid] = bfc[tid];
    const float4* hg = (const float4*)(g_h1 + (size_t)row0 * HH);
#pragma unroll
    for (int j = 0; j < 4; j++)
        ((float4*)h1s)[tid + 256 * j] = hg[tid + 256 * j];
    __syncthreads();

    int o  = tid & 31;
    int rg = tid >> 5;               // 8 groups x 4 rows
    int tb = row0 % TT;
#pragma unroll
    for (int i = 0; i < 4; i++) {
        int r = rg * 4 + i;
        int t = tb + r;
        float res;
        if (t < L) {
            float acc = 0.f;
#pragma unroll
            for (int k = 0; k < HH; k++)
                acc = fmaf(wfcT[k * 33 + o], h1s[r * HH + k], acc);
            res = acc + bfcs[o];
        } else {
            res = bfcs[o];
        }
        out[(size_t)(row0 + r) * OO + o] = res;
    }
}

// ---------------------------------------------------------------------------
extern "C" void kernel_launch(void* const* d_in, const int* in_sizes, int n_in,
                              void* d_out, int out_size) {
    const float* x     = (const float*)d_in[0];
    const int*   len   = (const int*)  d_in[1];
    const float* Wih0  = (const float*)d_in[2];
    const float* Whh0  = (const float*)d_in[3];
    const float* bih0  = (const float*)d_in[4];
    const float* bhh0  = (const float*)d_in[5];
    const float* Wih1  = (const float*)d_in[6];
    const float* Whh1  = (const float*)d_in[7];
    const float* bih1  = (const float*)d_in[8];
    const float* bhh1  = (const float*)d_in[9];
    const float* Wfc   = (const float*)d_in[10];
    const float* bfc   = (const float*)d_in[11];
    float* out = (float*)d_out;

    static_assert(2 * 64 * XPAD * 4 == 67584, "smem size");
    cudaFuncSetAttribute(xproj_kernel, cudaFuncAttributeMaxDynamicSharedMemorySize, 67584);
    xproj_kernel<<<(BB * TT) / 128, 256, 67584>>>(x, Wih0, bih0, bhh0);
    scan_kernel<<<BB, 384>>>(Whh0, Wih1, Whh1, bih1, bhh1, len);
    fc_kernel<<<(BB * TT) / 32, 256>>>(Wfc, bfc, len, out);
}